// round 17
// baseline (speedup 1.0000x reference)
#include <cuda_runtime.h>
#include <math.h>

// ---------------------------------------------------------------------------
// HMM forward (CgpHmmCell, nCodons=2), 24 states, T=2000, batch=2048.
// Transposed layout: one lane owns a full 24-state vector (12 f32x2 pairs);
// zero cross-lane exchange; fwd/bwd exact time split.  E rows compressed to
// 56B (5 f32x2 pairs + 7 bf16 + exact 1/6), stride 80B.
// R14: TWO independent rows per lane, interleaved per step — LDS/FMA2/ALU all
// pipeline across the chains (unlike shfl), hiding each other's latency.
// 64 warps = 64 CTAs x 32 threads.  Exact power-of-2 renorm every 20 steps.
// ---------------------------------------------------------------------------

typedef unsigned long long u64;

__device__ u64 g_WFp[19];            // fwd packed weights
__device__ u64 g_WBp[21];            // bwd packed weights
__device__ u64 g_piP[12];            // packed softmax(init), pair order
__device__ __align__(16) unsigned char g_BtE[216 * 80];  // compressed E rows
__device__ u64 g_vecP[4096][12];     // half-results (packed)
__device__ float g_Kv[4096];         // accumulated exponents

__constant__ int c_rcnt[24] = {2,1,1,4,1,1,3,1,1,2,1,1,1,2,1,1,2,1,1,2,1,1,2,1};
__constant__ int c_rcols[24][4] = {
  {0,1,0,0},{2,0,0,0},{3,0,0,0},{4,14,7,10},{5,0,0,0},{6,0,0,0},{7,17,10,0},
  {8,0,0,0},{9,0,0,0},{20,10,0,0},{11,0,0,0},{12,0,0,0},{13,0,0,0},{13,23,0,0},
  {15,0,0,0},{16,0,0,0},{4,14,0,0},{18,0,0,0},{19,0,0,0},{7,17,0,0},{21,0,0,0},
  {22,0,0,0},{10,20,0,0},{23,0,0,0}};
__constant__ int c_perm[24] = {0,1, 2,3, 4,14, 5,15, 6,16, 7,17, 8,18, 9,19,
                               10,20, 11,21, 12,22, 13,23};

__device__ __forceinline__ u64 pk2(float lo, float hi) {
  return ((u64)__float_as_uint(hi) << 32) | (u64)__float_as_uint(lo);
}
__device__ __forceinline__ unsigned bf16of(float v) {   // RN-even bf16 bits
  unsigned b = __float_as_uint(v);
  unsigned lsb = (b >> 16) & 1u;
  return (b + 0x7FFFu + lsb) >> 16;
}

// ---------------------------------------------------------------------------
// merged setup: blocks 0..215 build E rows; block 216 builds A/weights/pi
// ---------------------------------------------------------------------------
__global__ void setup_kernel(const float* __restrict__ w,
                             const float* __restrict__ ew,
                             const float* __restrict__ ik) {
  __shared__ float V[24][24];
  __shared__ float A[24][24];
  __shared__ float v[24];
  int tid = threadIdx.x;                       // 32 threads

  if (blockIdx.x < 216) {
    int ctx = blockIdx.x;
    int s = tid;
    if (s < 24) {
      int pp = ctx / 36, rm = ctx - pp * 36;
      int p = rm / 6, c = rm - p * 6;
      float val = 1.f / 6.f;
      if (s < 17 && pp < 4 && p < 4 && c < 4) {
        const float* e = ew + (((s * 4) + pp) * 4 + p) * 4;
        float m = fmaxf(fmaxf(e[0], e[1]), fmaxf(e[2], e[3]));
        float Z = __expf(e[0] - m) + __expf(e[1] - m) +
                  __expf(e[2] - m) + __expf(e[3] - m);
        val = __expf(e[c] - m) / Z;
      }
      v[s] = val;
    }
    __syncwarp();
    if (s == 0) {
      u64* row = (u64*)(g_BtE + ctx * 80);
      row[0] = pk2(v[0], v[1]);
      row[1] = pk2(v[2], v[3]);
      row[2] = pk2(v[4], v[14]);
      row[3] = pk2(v[5], v[15]);
      row[4] = pk2(v[6], v[16]);
      unsigned qa_lo = bf16of(v[7])  | (bf16of(v[8])  << 16);
      unsigned qa_hi = bf16of(v[9])  | (bf16of(v[10]) << 16);
      unsigned qb_lo = bf16of(v[11]) | (bf16of(v[12]) << 16);
      unsigned qb_hi = bf16of(v[13]);
      row[5] = ((u64)qa_hi << 32) | qa_lo;
      row[6] = ((u64)qb_hi << 32) | qb_lo;
    }
    return;
  }

  // ---- transition block ----------------------------------------------------
  for (int i = tid; i < 576; i += 32) {
    ((float*)V)[i] = 0.f;
    ((float*)A)[i] = 0.f;
  }
  __syncwarp();
  if (tid == 0) {
    float w12 = w[12];
    V[0][0]  = 1.f - w[0]; V[0][1]  = w[0];
    V[1][2]  = 1.f;        V[2][3]  = 1.f;
    V[3][4]  = w[1];       V[6][7]  = w[2];
    V[4][5]  = 1.f; V[7][8] = 1.f; V[5][6] = 1.f; V[8][9] = 1.f;
    V[3][14] = w[3]; V[6][17] = w[4]; V[9][20] = w[5];
    V[9][10] = 1.f - w[5];
    V[14][15] = 1.f; V[17][18] = 1.f; V[20][21] = 1.f;
    V[15][16] = 1.f; V[18][19] = 1.f; V[21][22] = 1.f;
    V[16][4] = w[6]; V[19][7] = w[7]; V[22][10] = w[8];
    V[16][14] = 1.f - w[9]; V[19][17] = 1.f - w[10]; V[22][20] = 1.f - w[11];
    V[3][7]  = 1.f - w12 * w12;
    V[3][10] = 1.f - w12 * w12 * w12;
    V[6][10] = 1.f - w12 * w12;
    V[10][11] = 1.f; V[11][12] = 1.f; V[12][13] = 1.f;
    V[13][13] = 1.f; V[13][23] = 1.f; V[23][23] = 1.f;
  }
  __syncwarp();
  if (tid < 24) {
    int n = c_rcnt[tid];
    float m = -1e30f;
    for (int i = 0; i < n; ++i) m = fmaxf(m, V[tid][c_rcols[tid][i]]);
    float Z = 0.f;
    for (int i = 0; i < n; ++i) Z += __expf(V[tid][c_rcols[tid][i]] - m);
    for (int i = 0; i < n; ++i) {
      int c = c_rcols[tid][i];
      A[tid][c] = __expf(V[tid][c] - m) / Z;
    }
  }
  __syncwarp();
  if (tid == 0) {
    float W0=A[0][0],  W1=A[0][1],  W2=A[1][2],  W3=A[2][3],  W4=A[3][4];
    float W5=A[16][4], W6=A[4][5],  W7=A[5][6],  W8=A[3][7],  W9=A[6][7];
    float W10=A[19][7],W11=A[7][8], W12=A[8][9], W13=A[3][10],W14=A[6][10];
    float W15=A[9][10],W16=A[22][10],W17=A[10][11],W18=A[11][12],W19=A[12][13];
    float W20=A[13][13],W21=A[3][14],W22=A[16][14],W23=A[14][15],W24=A[15][16];
    float W25=A[6][17],W26=A[19][17],W27=A[17][18],W28=A[18][19],W29=A[9][20];
    float W30=A[22][20],W31=A[20][21],W32=A[21][22],W33=A[13][23],W34=A[23][23];
    g_WFp[0]=pk2(W0,W1);   g_WFp[1]=pk2(W2,W3);   g_WFp[2]=pk2(W4,W21);
    g_WFp[3]=pk2(W5,W22);  g_WFp[4]=pk2(W6,W23);  g_WFp[5]=pk2(W7,W24);
    g_WFp[6]=pk2(W8,0.f);  g_WFp[7]=pk2(W9,W25);  g_WFp[8]=pk2(W10,W26);
    g_WFp[9]=pk2(W11,W27); g_WFp[10]=pk2(W12,W28);g_WFp[11]=pk2(W13,0.f);
    g_WFp[12]=pk2(W14,0.f);g_WFp[13]=pk2(W15,W29);g_WFp[14]=pk2(W16,W30);
    g_WFp[15]=pk2(W17,W31);g_WFp[16]=pk2(W18,W32);g_WFp[17]=pk2(W19,W33);
    g_WFp[18]=pk2(W20,W34);
    g_WBp[0]=pk2(W0,W2);   g_WBp[1]=pk2(W1,0.f);  g_WBp[2]=pk2(W3,W4);
    g_WBp[3]=pk2(0.f,W8);  g_WBp[4]=pk2(0.f,W13); g_WBp[5]=pk2(0.f,W21);
    g_WBp[6]=pk2(W6,W23);  g_WBp[7]=pk2(W7,W24);  g_WBp[8]=pk2(W9,W5);
    g_WBp[9]=pk2(W14,W22); g_WBp[10]=pk2(W25,0.f);g_WBp[11]=pk2(W11,W27);
    g_WBp[12]=pk2(W12,W28);g_WBp[13]=pk2(W15,W10);g_WBp[14]=pk2(W29,W26);
    g_WBp[15]=pk2(W17,W31);g_WBp[16]=pk2(W18,W32);g_WBp[17]=pk2(W19,W16);
    g_WBp[18]=pk2(0.f,W30);g_WBp[19]=pk2(W20,W34);g_WBp[20]=pk2(W33,0.f);
    float pi[24];
    float m = -1e30f;
    for (int s = 0; s < 24; ++s) m = fmaxf(m, ik[s]);
    float Z = 0.f;
    for (int s = 0; s < 24; ++s) Z += __expf(ik[s] - m);
    for (int s = 0; s < 24; ++s) pi[s] = __expf(ik[s] - m) / Z;
    for (int k = 0; k < 12; ++k)
      g_piP[k] = pk2(pi[c_perm[2*k]], pi[c_perm[2*k+1]]);
  }
}

// ---------------------------------------------------------------------------
#define ULO(x) ((unsigned)(x))
#define UHI(x) ((unsigned)((x) >> 32))
#define PKU(d, lo, hi) \
  asm("mov.b64 %0, {%1, %2};" : "=l"(d) : "r"(lo), "r"(hi))
#define FMA2(d, a, b, c) \
  asm("fma.rn.f32x2 %0, %1, %2, %3;" : "=l"(d) : "l"(a), "l"(b), "l"(c))
#define MUL2(d, a, b) \
  asm("mul.rn.f32x2 %0, %1, %2;" : "=l"(d) : "l"(a), "l"(b))
#define ADD2(d, a, b) \
  asm("add.rn.f32x2 %0, %1, %2;" : "=l"(d) : "l"(a), "l"(b))
#define FLOAT_OF(u) __uint_as_float(u)

#define ELOAD_TO(U, CTX) {                                                  \
  const unsigned char* _pb = sBt + (CTX) * 80;                              \
  ulonglong2 _y0 = *(const ulonglong2*)_pb;                                 \
  ulonglong2 _y1 = *(const ulonglong2*)(_pb + 16);                          \
  ulonglong2 _y2 = *(const ulonglong2*)(_pb + 32);                          \
  u64 _y3 = *(const u64*)(_pb + 48);                                        \
  U##0 = _y0.x; U##1 = _y0.y; U##2 = _y1.x; U##3 = _y1.y;                   \
  U##4 = _y2.x; U##5 = _y2.y; U##6 = _y3; }

#define EAPPLY_CORE(Q, U, S0,S1,S2,S3,S4,S5,S6,S7,S8,S9,S10,S11) {          \
  unsigned _wA = ULO(U##5), _wB = UHI(U##5);                                \
  unsigned _wC = ULO(U##6), _wD = UHI(U##6);                                \
  u64 _E5,_E6,_E7,_E8,_E9,_E10,_E11;                                        \
  PKU(_E5,  _wA << 16,          SIXF);                                      \
  PKU(_E6,  _wA & 0xFFFF0000u,  SIXF);                                      \
  PKU(_E7,  _wB << 16,          SIXF);                                      \
  PKU(_E8,  _wB & 0xFFFF0000u,  SIXF);                                      \
  PKU(_E9,  _wC << 16,          SIXF);                                      \
  PKU(_E10, _wC & 0xFFFF0000u,  SIXF);                                      \
  PKU(_E11, _wD << 16,          SIXF);                                      \
  u64 _r0,_r1,_r2,_r3,_r4,_r5,_r6,_r7,_r8,_r9,_r10,_r11;                    \
  MUL2(_r0, S0, U##0);  MUL2(_r1, S1, U##1);  MUL2(_r2, S2, U##2);          \
  MUL2(_r3, S3, U##3);  MUL2(_r4, S4, U##4);  MUL2(_r5, S5, _E5);           \
  MUL2(_r6, S6, _E6);   MUL2(_r7, S7, _E7);   MUL2(_r8, S8, _E8);           \
  MUL2(_r9, S9, _E9);   MUL2(_r10, S10, _E10); MUL2(_r11, S11, _E11);       \
  Q##0=_r0; Q##1=_r1; Q##2=_r2; Q##3=_r3; Q##4=_r4; Q##5=_r5;               \
  Q##6=_r6; Q##7=_r7; Q##8=_r8; Q##9=_r9; Q##10=_r10; Q##11=_r11; }

#define FSTEP_P(Q, UIN, ULD, CTXN) {                                        \
  ELOAD_TO(ULD, CTXN)                                                       \
  u64 Fa0, Fa12, Fa3, Fa6, Fa9, Fa16, Fa19, Fa22, Fc;                       \
  PKU(Fa0,  ULO(Q##0),  ULO(Q##0));                                         \
  PKU(Fa12, UHI(Q##0),  ULO(Q##1));                                         \
  PKU(Fa3,  UHI(Q##1),  UHI(Q##1));                                         \
  PKU(Fa6,  ULO(Q##4),  ULO(Q##4));                                         \
  PKU(Fa9,  ULO(Q##7),  ULO(Q##7));                                         \
  PKU(Fa16, UHI(Q##4),  UHI(Q##4));                                         \
  PKU(Fa19, UHI(Q##7),  UHI(Q##7));                                         \
  PKU(Fa22, UHI(Q##10), UHI(Q##10));                                        \
  PKU(Fc,   ULO(Q##10), ULO(Q##11));                                        \
  u64 t0, t2, t5, t8, t11;                                                  \
  MUL2(t0, WF0, Fa0);                                                       \
  MUL2(t2, WF2, Fa3);  FMA2(t2, WF3, Fa16, t2);                             \
  MUL2(t5, WF6, Fa3);  FMA2(t5, WF7, Fa6, t5);  FMA2(t5, WF8, Fa19, t5);    \
  MUL2(t8, WF11, Fa3); FMA2(t8, WF12, Fa6, t8);                             \
  FMA2(t8, WF13, Fa9, t8); FMA2(t8, WF14, Fa22, t8);                        \
  MUL2(t11, WF17, Fc); FMA2(t11, WF18, Q##11, t11);                         \
  EAPPLY_CORE(Q, UIN, t0, Fa12, t2, Q##2, Q##3, t5, Q##5, Q##6, t8,         \
              Q##8, Q##9, t11)                                              \
}

#define BMAT_CORE(Q)                                                        \
  u64 G0,G1,G2,G3,G4,G5,G6,G7,G8,G9,G10,G11,G12,G13;                        \
  PKU(G0,  ULO(Q##0),  ULO(Q##1));                                          \
  PKU(G1,  UHI(Q##0),  UHI(Q##0));                                          \
  PKU(G2,  UHI(Q##1),  ULO(Q##2));                                          \
  PKU(G3,  ULO(Q##5),  ULO(Q##5));                                          \
  PKU(G4,  ULO(Q##8),  ULO(Q##8));                                          \
  PKU(G5,  UHI(Q##2),  UHI(Q##2));                                          \
  PKU(G6,  ULO(Q##5),  ULO(Q##2));                                          \
  PKU(G7,  ULO(Q##8),  UHI(Q##2));                                          \
  PKU(G8,  UHI(Q##5),  UHI(Q##5));                                          \
  PKU(G9,  ULO(Q##8),  ULO(Q##5));                                          \
  PKU(G10, UHI(Q##8),  UHI(Q##5));                                          \
  PKU(G11, ULO(Q##11), ULO(Q##8));                                          \
  PKU(G12, UHI(Q##8),  UHI(Q##8));                                          \
  PKU(G13, UHI(Q##11), UHI(Q##11));                                         \
  u64 t0, t1, t4, t7, t10, t11;                                             \
  MUL2(t0, WB0, G0);  FMA2(t0, WB1, G1, t0);                                \
  MUL2(t1, WB2, G2);  FMA2(t1, WB3, G3, t1);                                \
  FMA2(t1, WB4, G4, t1); FMA2(t1, WB5, G5, t1);                             \
  MUL2(t4, WB8, G6);  FMA2(t4, WB9, G7, t4);  FMA2(t4, WB10, G8, t4);       \
  MUL2(t7, WB13, G9); FMA2(t7, WB14, G10, t7);                              \
  MUL2(t10, WB17, G11); FMA2(t10, WB18, G12, t10);                          \
  MUL2(t11, WB19, Q##11); FMA2(t11, WB20, G13, t11);

#define BSTEP_P(Q, UIN, ULD, CTXN) {                                        \
  ELOAD_TO(ULD, CTXN)                                                       \
  BMAT_CORE(Q)                                                              \
  EAPPLY_CORE(Q, UIN, t0, t1, Q##3, Q##4, t4, Q##6, Q##7, t7, Q##9,         \
              Q##10, t10, t11)                                              \
}

#define RENORMP(Q, KV) {                                                    \
  u64 _s0, _s1, _s2, _s3, _s4, _s5, _sa, _sb, _sc2, _st;                    \
  ADD2(_s0, Q##0, Q##1);  ADD2(_s1, Q##2, Q##3);  ADD2(_s2, Q##4, Q##5);    \
  ADD2(_s3, Q##6, Q##7);  ADD2(_s4, Q##8, Q##9);  ADD2(_s5, Q##10, Q##11);  \
  ADD2(_sa, _s0, _s1); ADD2(_sb, _s2, _s3); ADD2(_sc2, _s4, _s5);           \
  ADD2(_st, _sa, _sb); ADD2(_st, _st, _sc2);                                \
  float _z = FLOAT_OF(ULO(_st)) + FLOAT_OF(UHI(_st));                       \
  int _ez = ((__float_as_int(_z) >> 23) & 0xff) - 127;                      \
  float _sc = __int_as_float((127 - _ez) << 23);                            \
  KV += _ez;                                                                \
  u64 _SC; PKU(_SC, __float_as_uint(_sc), __float_as_uint(_sc));            \
  MUL2(Q##0, Q##0, _SC);  MUL2(Q##1, Q##1, _SC);  MUL2(Q##2, Q##2, _SC);    \
  MUL2(Q##3, Q##3, _SC);  MUL2(Q##4, Q##4, _SC);  MUL2(Q##5, Q##5, _SC);    \
  MUL2(Q##6, Q##6, _SC);  MUL2(Q##7, Q##7, _SC);  MUL2(Q##8, Q##8, _SC);    \
  MUL2(Q##9, Q##9, _SC);  MUL2(Q##10, Q##10, _SC); MUL2(Q##11, Q##11, _SC); }

// dual-row fwd group: 4 steps for rows X and Y, interleaved per step
#define GROUPF2(g) {                                                        \
  int4 _nX = spX[(g) + 1]; int4 _nY = spY[(g) + 1];                         \
  int _xc1 = prvX.w*36 + curX.x*6 + curX.y;                                 \
  int _xc2 = curX.x*36 + curX.y*6 + curX.z;                                 \
  int _xc3 = curX.y*36 + curX.z*6 + curX.w;                                 \
  int _xc4 = curX.z*36 + curX.w*6 + _nX.x;                                  \
  int _yc1 = prvY.w*36 + curY.x*6 + curY.y;                                 \
  int _yc2 = curY.x*36 + curY.y*6 + curY.z;                                 \
  int _yc3 = curY.y*36 + curY.z*6 + curY.w;                                 \
  int _yc4 = curY.z*36 + curY.w*6 + _nY.x;                                  \
  FSTEP_P(qX, UXB, UXA, _xc1)  FSTEP_P(qY, UYB, UYA, _yc1)                  \
  FSTEP_P(qX, UXA, UXB, _xc2)  FSTEP_P(qY, UYA, UYB, _yc2)                  \
  FSTEP_P(qX, UXB, UXA, _xc3)  FSTEP_P(qY, UYB, UYA, _yc3)                  \
  FSTEP_P(qX, UXA, UXB, _xc4)  FSTEP_P(qY, UYA, UYB, _yc4)                  \
  prvX = curX; curX = _nX; prvY = curY; curY = _nY; }

// dual-row bwd group (descending)
#define GROUPB2(g) {                                                        \
  int4 _pX = spX[(g) - 1]; int4 _pY = spY[(g) - 1];                         \
  int _xc2 = curX.x*36 + curX.y*6 + curX.z;                                 \
  int _xc1 = _pX.w*36 + curX.x*6 + curX.y;                                  \
  int _xc0 = _pX.z*36 + _pX.w*6 + curX.x;                                   \
  int _xcn = _pX.y*36 + _pX.z*6 + _pX.w;                                    \
  int _yc2 = curY.x*36 + curY.y*6 + curY.z;                                 \
  int _yc1 = _pY.w*36 + curY.x*6 + curY.y;                                  \
  int _yc0 = _pY.z*36 + _pY.w*6 + curY.x;                                   \
  int _ycn = _pY.y*36 + _pY.z*6 + _pY.w;                                    \
  BSTEP_P(qX, UXB, UXA, _xc2)  BSTEP_P(qY, UYB, UYA, _yc2)                  \
  BSTEP_P(qX, UXA, UXB, _xc1)  BSTEP_P(qY, UYA, UYB, _yc1)                  \
  BSTEP_P(qX, UXB, UXA, _xc0)  BSTEP_P(qY, UYB, UYA, _yc0)                  \
  BSTEP_P(qX, UXA, UXB, _xcn)  BSTEP_P(qY, UYA, UYB, _ycn)                  \
  curX = _pX; curY = _pY; }

#define STOREQ(Q, TASK, KV) {                                               \
  u64* _ov = g_vecP[TASK];                                                  \
  _ov[0]=Q##0; _ov[1]=Q##1; _ov[2]=Q##2; _ov[3]=Q##3; _ov[4]=Q##4;          \
  _ov[5]=Q##5; _ov[6]=Q##6; _ov[7]=Q##7; _ov[8]=Q##8; _ov[9]=Q##9;          \
  _ov[10]=Q##10; _ov[11]=Q##11;                                             \
  g_Kv[TASK] = (float)KV; }

__global__ void __launch_bounds__(32)
scan_kernel(const int* __restrict__ seq, int T, int batch) {
  static __shared__ __align__(16) unsigned char sBt[216 * 80];
  int lane = threadIdx.x;
  {
    const float4* srcp = (const float4*)g_BtE;
    float4* dstp = (float4*)sBt;
    for (int i = lane; i < 216 * 5; i += 32) dstp[i] = srcp[i];
  }
  __syncwarp();

  const unsigned SIXF = 0x3E2AAAABu;     // exact f32 bits of 1/6 (RN)

  int nf = (int)gridDim.x >> 1;          // fwd CTAs
  int isF = blockIdx.x < nf;
  int bb = isF ? blockIdx.x : blockIdx.x - nf;
  int rowX = bb * 64 + lane;             // two rows per lane
  int rowY = rowX + 32;
  const int4* spX = (const int4*)(seq + (long long)rowX * T);
  const int4* spY = (const int4*)(seq + (long long)rowY * T);
  int taskX = isF ? rowX : batch + rowX;
  int taskY = isF ? rowY : batch + rowY;

  u64 qX0,qX1,qX2,qX3,qX4,qX5,qX6,qX7,qX8,qX9,qX10,qX11;
  u64 qY0,qY1,qY2,qY3,qY4,qY5,qY6,qY7,qY8,qY9,qY10,qY11;
  u64 UXA0,UXA1,UXA2,UXA3,UXA4,UXA5,UXA6;
  u64 UXB0,UXB1,UXB2,UXB3,UXB4,UXB5,UXB6;
  u64 UYA0,UYA1,UYA2,UYA3,UYA4,UYA5,UYA6;
  u64 UYB0,UYB1,UYB2,UYB3,UYB4,UYB5,UYB6;
  int KX = 0, KY = 0;
  int HC = T / 8;                 // 250 groups per half
  int n5 = (HC - 1) / 5;          // 49
  int rem = (HC - 1) - n5 * 5;    // 4

  if (isF) {
    u64 WF0=g_WFp[0], WF2=g_WFp[2], WF3=g_WFp[3], WF6=g_WFp[6];
    u64 WF7=g_WFp[7], WF8=g_WFp[8], WF11=g_WFp[11], WF12=g_WFp[12];
    u64 WF13=g_WFp[13], WF14=g_WFp[14], WF17=g_WFp[17], WF18=g_WFp[18];

    int4 curX = spX[0], curY = spY[0];
    ELOAD_TO(UXB, 168 + curX.x)
    ELOAD_TO(UYB, 168 + curY.x)
    ELOAD_TO(UXA, 144 + curX.x*6 + curX.y)
    ELOAD_TO(UYA, 144 + curY.x*6 + curY.y)
    {
      u64 p0=g_piP[0], p1=g_piP[1], p2=g_piP[2], p3=g_piP[3];
      u64 p4=g_piP[4], p5=g_piP[5], p6=g_piP[6], p7=g_piP[7];
      u64 p8=g_piP[8], p9=g_piP[9], p10=g_piP[10], p11=g_piP[11];
      EAPPLY_CORE(qX, UXB, p0,p1,p2,p3,p4,p5,p6,p7,p8,p9,p10,p11)   // t=0
      EAPPLY_CORE(qY, UYB, p0,p1,p2,p3,p4,p5,p6,p7,p8,p9,p10,p11)
    }
    int4 nX0 = spX[1], nY0 = spY[1];
    {
      int xc2 = curX.x*36 + curX.y*6 + curX.z;
      int xc3 = curX.y*36 + curX.z*6 + curX.w;
      int xc4 = curX.z*36 + curX.w*6 + nX0.x;
      int yc2 = curY.x*36 + curY.y*6 + curY.z;
      int yc3 = curY.y*36 + curY.z*6 + curY.w;
      int yc4 = curY.z*36 + curY.w*6 + nY0.x;
      FSTEP_P(qX, UXA, UXB, xc2)  FSTEP_P(qY, UYA, UYB, yc2)   // t=1
      FSTEP_P(qX, UXB, UXA, xc3)  FSTEP_P(qY, UYB, UYA, yc3)   // t=2
      FSTEP_P(qX, UXA, UXB, xc4)  FSTEP_P(qY, UYA, UYB, yc4)   // t=3
    }
    int4 prvX = curX, prvY = curY;
    curX = nX0; curY = nY0;
    int g = 1;
    for (int it = 0; it < n5; ++it) {
      GROUPF2(g); GROUPF2(g + 1); GROUPF2(g + 2); GROUPF2(g + 3);
      GROUPF2(g + 4);
      g += 5;
      RENORMP(qX, KX);
      RENORMP(qY, KY);
    }
    for (int r = 0; r < rem; ++r) { GROUPF2(g); ++g; }
  } else {
    u64 WB0=g_WBp[0], WB1=g_WBp[1], WB2=g_WBp[2], WB3=g_WBp[3];
    u64 WB4=g_WBp[4], WB5=g_WBp[5], WB8=g_WBp[8], WB9=g_WBp[9];
    u64 WB10=g_WBp[10], WB13=g_WBp[13], WB14=g_WBp[14];
    u64 WB17=g_WBp[17], WB18=g_WBp[18], WB19=g_WBp[19], WB20=g_WBp[20];

    int CH = T / 4;                       // 500 chunks
    int4 curX = spX[CH - 1], curY = spY[CH - 1];
    int4 pX0 = spX[CH - 2], pY0 = spY[CH - 2];
    ELOAD_TO(UXB, curX.y*36 + curX.z*6 + curX.w)
    ELOAD_TO(UYB, curY.y*36 + curY.z*6 + curY.w)
    ELOAD_TO(UXA, curX.x*36 + curX.y*6 + curX.z)
    ELOAD_TO(UYA, curY.x*36 + curY.y*6 + curY.z)
    {
      u64 ONEP; PKU(ONEP, 0x3F800000u, 0x3F800000u);
      EAPPLY_CORE(qX, UXB, ONEP,ONEP,ONEP,ONEP,ONEP,ONEP,ONEP,ONEP,ONEP,
                  ONEP,ONEP,ONEP)                          // t = T-1: m = E
      EAPPLY_CORE(qY, UYB, ONEP,ONEP,ONEP,ONEP,ONEP,ONEP,ONEP,ONEP,ONEP,
                  ONEP,ONEP,ONEP)
    }
    {
      int xc1997 = pX0.w*36 + curX.x*6 + curX.y;
      int xc1996 = pX0.z*36 + pX0.w*6 + curX.x;
      int xc1995 = pX0.y*36 + pX0.z*6 + pX0.w;
      int yc1997 = pY0.w*36 + curY.x*6 + curY.y;
      int yc1996 = pY0.z*36 + pY0.w*6 + curY.x;
      int yc1995 = pY0.y*36 + pY0.z*6 + pY0.w;
      BSTEP_P(qX, UXA, UXB, xc1997)  BSTEP_P(qY, UYA, UYB, yc1997)
      BSTEP_P(qX, UXB, UXA, xc1996)  BSTEP_P(qY, UYB, UYA, yc1996)
      BSTEP_P(qX, UXA, UXB, xc1995)  BSTEP_P(qY, UYA, UYB, yc1995)
    }
    curX = pX0; curY = pY0;
    int g = CH - 2;                       // 498
    for (int it = 0; it < n5; ++it) {
      GROUPB2(g); GROUPB2(g - 1); GROUPB2(g - 2); GROUPB2(g - 3);
      GROUPB2(g - 4);
      g -= 5;
      RENORMP(qX, KX);
      RENORMP(qY, KY);
    }
    for (int r = 0; r < rem; ++r) { GROUPB2(g); --g; }
    // final conversion: u = A m (no emission), each row
    {
      BMAT_CORE(qX)
      u64 _n2=qX3, _n3=qX4, _n5=qX6, _n6=qX7, _n8=qX9, _n9=qX10;
      qX0=t0; qX1=t1; qX2=_n2; qX3=_n3; qX4=t4; qX5=_n5;
      qX6=_n6; qX7=t7; qX8=_n8; qX9=_n9; qX10=t10; qX11=t11;
    }
    {
      BMAT_CORE(qY)
      u64 _n2=qY3, _n3=qY4, _n5=qY6, _n6=qY7, _n8=qY9, _n9=qY10;
      qY0=t0; qY1=t1; qY2=_n2; qY3=_n3; qY4=t4; qY5=_n5;
      qY6=_n6; qY7=t7; qY8=_n8; qY9=_n9; qY10=t10; qY11=t11;
    }
  }

  STOREQ(qX, taskX, KX)
  STOREQ(qY, taskY, KY)
}

// ---------------------------------------------------------------------------
__global__ void combine_kernel(float* __restrict__ out, int batch) {
  int r = blockIdx.x * 128 + threadIdx.x;
  if (r >= batch) return;
  const u64* fa = g_vecP[r];
  const u64* fb = g_vecP[r + batch];
  float dot = 0.f;
#pragma unroll
  for (int k = 0; k < 12; ++k) {
    u64 a = fa[k], b = fb[k];
    dot = fmaf(FLOAT_OF(ULO(a)), FLOAT_OF(ULO(b)), dot);
    dot = fmaf(FLOAT_OF(UHI(a)), FLOAT_OF(UHI(b)), dot);
  }
  out[r] = (__log2f(dot) + g_Kv[r] + g_Kv[r + batch]) *
           0.69314718055994530942f;
}

// ---------------------------------------------------------------------------
extern "C" void kernel_launch(void* const* d_in, const int* in_sizes, int n_in,
                              void* d_out, int out_size) {
  const float* w  = (const float*)d_in[0];   // transition_kernel (240)
  const float* ew = (const float*)d_in[1];   // emission_kernel (1088)
  const float* ik = (const float*)d_in[2];   // init_kernel (24)
  const int* seq  = (const int*)d_in[3];     // (batch, T)
  float* out = (float*)d_out;

  int batch = out_size;                      // 2048
  int T = in_sizes[3] / batch;               // 2000

  setup_kernel<<<217, 32>>>(w, ew, ik);
  scan_kernel<<<(batch / 64) * 2, 32>>>(seq, T, batch);
  combine_kernel<<<(batch + 127) / 128, 128>>>(out, batch);
}